// round 1
// baseline (speedup 1.0000x reference)
#include <cuda_runtime.h>
#include <cstdint>

#define S4      24
#define S3STR   24
#define S2STR   576
#define S1STR   13824
#define STOT    331776          // 24^4
#define CIN     8
#define COUT    16
#define NTAP    81
#define XIMG    (CIN * STOT)    // per-batch x elements
#define OIMG    (COUT * STOT)   // per-batch out elements
// work decomposition: 4 batch-pairs * 24*24*24 * 12 w-pairs
#define NWORK   (4 * 24 * 24 * 24 * 12)   // 663552

__device__ __forceinline__ unsigned long long dup2(float a) {
    unsigned long long d;
    asm("mov.b64 %0, {%1, %1};" : "=l"(d) : "f"(a));
    return d;
}
__device__ __forceinline__ unsigned long long pack2(float lo, float hi) {
    unsigned long long d;
    asm("mov.b64 %0, {%1, %2};" : "=l"(d) : "f"(lo), "f"(hi));
    return d;
}
__device__ __forceinline__ unsigned long long fma2(unsigned long long a,
                                                   unsigned long long b,
                                                   unsigned long long c) {
    unsigned long long d;
    asm("fma.rn.f32x2 %0, %1, %2, %3;" : "=l"(d) : "l"(a), "l"(b), "l"(c));
    return d;
}
__device__ __forceinline__ void unpack2(unsigned long long d, float& lo, float& hi) {
    asm("mov.b64 {%0, %1}, %2;" : "=f"(lo), "=f"(hi) : "l"(d));
}

__global__ __launch_bounds__(256)
void conv4d_kernel(const float* __restrict__ x,
                   const float* __restrict__ w,
                   const float* __restrict__ bias,
                   float* __restrict__ out) {
    // transposed weights in smem: wsm[(tap*CIN + cin)*COUT + o]
    // so an output-channel pair (2op, 2op+1) is one aligned 8-byte LDS.64 broadcast
    __shared__ __align__(16) float wsm[NTAP * CIN * COUT];   // 41472 B

    for (int t = threadIdx.x; t < NTAP * CIN * COUT; t += blockDim.x) {
        int i = t / COUT;        // tap*CIN + cin
        int o = t - i * COUT;
        wsm[t] = w[o * (NTAP * CIN) + i];
    }
    __syncthreads();

    int gid = blockIdx.x * blockDim.x + threadIdx.x;
    if (gid >= NWORK) return;

    int wp = gid % 12;  int r = gid / 12;
    int s3 = r % 24;    r /= 24;
    int s2 = r % 24;    r /= 24;
    int s1 = r % 24;
    int bp = r / 24;                       // 0..3
    int w0 = 2 * wp;

    const float* __restrict__ xb0 = x + (size_t)bp       * XIMG;
    const float* __restrict__ xb1 = x + (size_t)(bp + 4) * XIMG;

    // accumulators: combo 0=(b0,w0) 1=(b0,w1) 2=(b1,w0) 3=(b1,w1); 8 o-pairs each
    unsigned long long acc[4][8];
    #pragma unroll
    for (int op = 0; op < 8; ++op) {
        unsigned long long bv = pack2(bias[2 * op], bias[2 * op + 1]);
        acc[0][op] = bv; acc[1][op] = bv; acc[2][op] = bv; acc[3][op] = bv;
    }

    #pragma unroll 1
    for (int k1 = 0; k1 < 3; ++k1) {
        int p1 = s1 + k1 - 1;
        if ((unsigned)p1 >= 24u) continue;
        #pragma unroll 1
        for (int k2 = 0; k2 < 3; ++k2) {
            int p2 = s2 + k2 - 1;
            if ((unsigned)p2 >= 24u) continue;
            #pragma unroll 1
            for (int k3 = 0; k3 < 3; ++k3) {
                int p3 = s3 + k3 - 1;
                if ((unsigned)p3 >= 24u) continue;
                int sbase = p1 * S1STR + p2 * S2STR + p3 * S3STR;
                int tap0  = ((k1 * 3 + k2) * 3 + k3) * 3;
                #pragma unroll
                for (int k4 = 0; k4 < 3; ++k4) {
                    int pw0 = w0 + k4 - 1;
                    bool v0 = (unsigned)pw0       < 24u;
                    bool v1 = (unsigned)(pw0 + 1) < 24u;
                    int xoff = sbase + pw0;
                    const float* wrow = wsm + (tap0 + k4) * (CIN * COUT);
                    #pragma unroll
                    for (int c = 0; c < CIN; ++c) {
                        int o = c * STOT + xoff;
                        float a00 = 0.f, a01 = 0.f, a10 = 0.f, a11 = 0.f;
                        if (v0) { a00 = xb0[o];     a10 = xb1[o];     }
                        if (v1) { a01 = xb0[o + 1]; a11 = xb1[o + 1]; }
                        unsigned long long x00 = dup2(a00);
                        unsigned long long x01 = dup2(a01);
                        unsigned long long x10 = dup2(a10);
                        unsigned long long x11 = dup2(a11);
                        const float* wc = wrow + c * COUT;
                        #pragma unroll
                        for (int op = 0; op < 8; ++op) {
                            unsigned long long w2 =
                                *reinterpret_cast<const unsigned long long*>(wc + 2 * op);
                            acc[0][op] = fma2(x00, w2, acc[0][op]);
                            acc[1][op] = fma2(x01, w2, acc[1][op]);
                            acc[2][op] = fma2(x10, w2, acc[2][op]);
                            acc[3][op] = fma2(x11, w2, acc[3][op]);
                        }
                    }
                }
            }
        }
    }

    // store: out[b][o][s1][s2][s3][w]
    int sb3 = s1 * S1STR + s2 * S2STR + s3 * S3STR;
    int ci = 0;
    #pragma unroll
    for (int bi = 0; bi < 2; ++bi) {
        int b = bp + 4 * bi;
        #pragma unroll
        for (int wi = 0; wi < 2; ++wi, ++ci) {
            size_t ob = (size_t)b * OIMG + (size_t)(sb3 + w0 + wi);
            #pragma unroll
            for (int op = 0; op < 8; ++op) {
                float lo, hi;
                unpack2(acc[ci][op], lo, hi);
                out[ob + (size_t)(2 * op)     * STOT] = lo;
                out[ob + (size_t)(2 * op + 1) * STOT] = hi;
            }
        }
    }
}

extern "C" void kernel_launch(void* const* d_in, const int* in_sizes, int n_in,
                              void* d_out, int out_size) {
    const float* x    = (const float*)d_in[0];
    const float* wgt  = (const float*)d_in[1];
    const float* bias = (const float*)d_in[2];
    float* out = (float*)d_out;
    (void)in_sizes; (void)n_in; (void)out_size;

    dim3 block(256);
    dim3 grid((NWORK + 255) / 256);   // 2592
    conv4d_kernel<<<grid, block>>>(x, wgt, bias, out);
}

// round 2
// speedup vs baseline: 1.0942x; 1.0942x over previous
#include <cuda_runtime.h>
#include <cstdint>

#define S4      24
#define S3STR   24
#define S2STR   576
#define S1STR   13824
#define STOT    331776          // 24^4
#define CIN     8
#define COUT    16
#define NTAP    81
#define XIMG    (CIN * STOT)
#define OIMG    (COUT * STOT)
// 4 batch-pairs * 24*24*24 * 12 w-pairs
#define NWORK   (4 * 24 * 24 * 24 * 12)   // 663552

typedef unsigned long long u64;

__device__ __forceinline__ u64 dup2(float a) {
    u64 d; asm("mov.b64 %0, {%1, %1};" : "=l"(d) : "f"(a)); return d;
}
__device__ __forceinline__ u64 pack2(float lo, float hi) {
    u64 d; asm("mov.b64 %0, {%1, %2};" : "=l"(d) : "f"(lo), "f"(hi)); return d;
}
__device__ __forceinline__ u64 fma2(u64 a, u64 b, u64 c) {
    u64 d; asm("fma.rn.f32x2 %0, %1, %2, %3;" : "=l"(d) : "l"(a), "l"(b), "l"(c));
    return d;
}
__device__ __forceinline__ void unpack2(u64 d, float& lo, float& hi) {
    asm("mov.b64 {%0, %1}, %2;" : "=f"(lo), "=f"(hi) : "l"(d));
}

__global__ __launch_bounds__(128, 3)
void conv4d_kernel(const float* __restrict__ x,
                   const float* __restrict__ w,
                   const float* __restrict__ bias,
                   float* __restrict__ out) {
    // wsm[(tap*CIN + cin)*COUT + o] : an o-pair-pair is one aligned LDS.128
    __shared__ __align__(16) float wsm[NTAP * CIN * COUT];   // 41472 B

    for (int t = threadIdx.x; t < NTAP * CIN * COUT; t += blockDim.x) {
        int i = t / COUT;
        int o = t - i * COUT;
        wsm[t] = w[o * (NTAP * CIN) + i];
    }
    __syncthreads();

    int gid = blockIdx.x * blockDim.x + threadIdx.x;
    if (gid >= NWORK) return;

    int wp = gid % 12;  int r = gid / 12;
    int s3 = r % 24;    r /= 24;
    int s2 = r % 24;    r /= 24;
    int s1 = r % 24;
    int bp = r / 24;                       // 0..3
    int w0 = 2 * wp;

    bool vlo = (wp != 0);     // position w0-1 valid
    bool vhi = (wp != 11);    // position w0+2 valid

    const float* __restrict__ xb0 = x + (size_t)bp       * XIMG;
    const float* __restrict__ xb1 = x + (size_t)(bp + 4) * XIMG;

    // acc[combo][op-pair]; combo: 0=(b0,w0) 1=(b0,w1) 2=(b1,w0) 3=(b1,w1)
    u64 acc[4][8];
    #pragma unroll
    for (int op = 0; op < 8; ++op) {
        u64 bv = pack2(bias[2 * op], bias[2 * op + 1]);
        acc[0][op] = bv; acc[1][op] = bv; acc[2][op] = bv; acc[3][op] = bv;
    }

    #pragma unroll 1
    for (int k1 = 0; k1 < 3; ++k1) {
        int p1 = s1 + k1 - 1;
        if ((unsigned)p1 >= 24u) continue;
        #pragma unroll 1
        for (int k2 = 0; k2 < 3; ++k2) {
            int p2 = s2 + k2 - 1;
            if ((unsigned)p2 >= 24u) continue;
            #pragma unroll 1
            for (int k3 = 0; k3 < 3; ++k3) {
                int p3 = s3 + k3 - 1;
                if ((unsigned)p3 >= 24u) continue;
                int xoff = p1 * S1STR + p2 * S2STR + p3 * S3STR + w0 - 1;
                int tap0 = ((k1 * 3 + k2) * 3 + k3) * 3;
                const float* wbase = wsm + tap0 * (CIN * COUT);
                #pragma unroll
                for (int c = 0; c < CIN; ++c) {
                    const float* p0 = xb0 + c * STOT + xoff;
                    const float* p1p = xb1 + c * STOT + xoff;
                    // 4 distinct w-positions, shared by the 3 k4 taps
                    float f00 = vlo ? p0[0]  : 0.f;
                    float f01 = p0[1];
                    float f02 = p0[2];
                    float f03 = vhi ? p0[3]  : 0.f;
                    float f10 = vlo ? p1p[0] : 0.f;
                    float f11 = p1p[1];
                    float f12 = p1p[2];
                    float f13 = vhi ? p1p[3] : 0.f;
                    u64 d0[4] = { dup2(f00), dup2(f01), dup2(f02), dup2(f03) };
                    u64 d1[4] = { dup2(f10), dup2(f11), dup2(f12), dup2(f13) };
                    #pragma unroll
                    for (int k4 = 0; k4 < 3; ++k4) {
                        const ulonglong2* wq = reinterpret_cast<const ulonglong2*>(
                            wbase + (k4 * CIN + c) * COUT);
                        u64 xa0 = d0[k4], xa1 = d0[k4 + 1];
                        u64 xb0v = d1[k4], xb1v = d1[k4 + 1];
                        #pragma unroll
                        for (int q = 0; q < 4; ++q) {
                            ulonglong2 wv = wq[q];
                            acc[0][2*q]   = fma2(xa0,  wv.x, acc[0][2*q]);
                            acc[0][2*q+1] = fma2(xa0,  wv.y, acc[0][2*q+1]);
                            acc[1][2*q]   = fma2(xa1,  wv.x, acc[1][2*q]);
                            acc[1][2*q+1] = fma2(xa1,  wv.y, acc[1][2*q+1]);
                            acc[2][2*q]   = fma2(xb0v, wv.x, acc[2][2*q]);
                            acc[2][2*q+1] = fma2(xb0v, wv.y, acc[2][2*q+1]);
                            acc[3][2*q]   = fma2(xb1v, wv.x, acc[3][2*q]);
                            acc[3][2*q+1] = fma2(xb1v, wv.y, acc[3][2*q+1]);
                        }
                    }
                }
            }
        }
    }

    // stores: pack the two w-positions into one float2 per (b, o)
    int sb3 = s1 * S1STR + s2 * S2STR + s3 * S3STR + w0;
    #pragma unroll
    for (int bi = 0; bi < 2; ++bi) {
        int b = bp + 4 * bi;
        float2* ob = reinterpret_cast<float2*>(out + (size_t)b * OIMG + sb3);
        #pragma unroll
        for (int op = 0; op < 8; ++op) {
            float lo0, hi0, lo1, hi1;
            unpack2(acc[bi * 2 + 0][op], lo0, hi0);   // w0:   (o, o+1)
            unpack2(acc[bi * 2 + 1][op], lo1, hi1);   // w0+1: (o, o+1)
            ob[(size_t)(2 * op)     * (STOT / 2)] = make_float2(lo0, lo1);
            ob[(size_t)(2 * op + 1) * (STOT / 2)] = make_float2(hi0, hi1);
        }
    }
}

extern "C" void kernel_launch(void* const* d_in, const int* in_sizes, int n_in,
                              void* d_out, int out_size) {
    const float* x    = (const float*)d_in[0];
    const float* wgt  = (const float*)d_in[1];
    const float* bias = (const float*)d_in[2];
    float* out = (float*)d_out;
    (void)in_sizes; (void)n_in; (void)out_size;

    dim3 block(128);
    dim3 grid((NWORK + 127) / 128);   // 5184
    conv4d_kernel<<<grid, block>>>(x, wgt, bias, out);
}

// round 3
// speedup vs baseline: 1.3232x; 1.2093x over previous
#include <cuda_runtime.h>
#include <cstdint>

#define S4      24
#define S3STR   24
#define S2STR   576
#define S1STR   13824
#define STOT    331776          // 24^4
#define CIN     8
#define COUT    16
#define NTAP    81
#define XIMG    (CIN * STOT)
#define OIMG    (COUT * STOT)
// 8 batches * 24*24*24 * 6 w-quads ; 663552 threads, /128 = 5184 blocks exactly
#define NWORK   (8 * 24 * 24 * 24 * 6)

typedef unsigned long long u64;

__device__ __forceinline__ u64 dup2(float a) {
    u64 d; asm("mov.b64 %0, {%1, %1};" : "=l"(d) : "f"(a)); return d;
}
__device__ __forceinline__ u64 pack2(float lo, float hi) {
    u64 d; asm("mov.b64 %0, {%1, %2};" : "=l"(d) : "f"(lo), "f"(hi)); return d;
}
__device__ __forceinline__ u64 fma2(u64 a, u64 b, u64 c) {
    u64 d; asm("fma.rn.f32x2 %0, %1, %2, %3;" : "=l"(d) : "l"(a), "l"(b), "l"(c));
    return d;
}
__device__ __forceinline__ void unpack2(u64 d, float& lo, float& hi) {
    asm("mov.b64 {%0, %1}, %2;" : "=f"(lo), "=f"(hi) : "l"(d));
}

__global__ __launch_bounds__(128, 4)
void conv4d_kernel(const float* __restrict__ x,
                   const float* __restrict__ w,
                   const float* __restrict__ bias,
                   float* __restrict__ out) {
    // wsm[(tap*CIN + cin)*COUT + o] : 4 o-pairs = one aligned LDS.128 broadcast
    __shared__ __align__(16) float wsm[NTAP * CIN * COUT];   // 41472 B

    for (int t = threadIdx.x; t < NTAP * CIN * COUT; t += blockDim.x) {
        int i = t / COUT;
        int o = t - i * COUT;
        wsm[t] = w[o * (NTAP * CIN) + i];
    }
    __syncthreads();

    int gid = blockIdx.x * blockDim.x + threadIdx.x;

    int wq = gid % 6;   int r = gid / 6;
    int s3 = r % 24;    r /= 24;
    int s2 = r % 24;    r /= 24;
    int s1 = r % 24;
    int b  = r / 24;                       // 0..7
    int w0 = 4 * wq;

    bool vlo = (wq != 0);     // x position w0-1 valid
    bool vhi = (wq != 5);     // x position w0+4 valid

    const float* __restrict__ xb = x + (size_t)b * XIMG;

    // acc[w][op] : w = s4 offset 0..3, op = output-channel pair (2op, 2op+1)
    u64 acc[4][8];
    #pragma unroll
    for (int op = 0; op < 8; ++op) {
        u64 bv = pack2(bias[2 * op], bias[2 * op + 1]);
        acc[0][op] = bv; acc[1][op] = bv; acc[2][op] = bv; acc[3][op] = bv;
    }

    #pragma unroll 1
    for (int k1 = 0; k1 < 3; ++k1) {
        int p1 = s1 + k1 - 1;
        if ((unsigned)p1 >= 24u) continue;
        #pragma unroll 1
        for (int k2 = 0; k2 < 3; ++k2) {
            int p2 = s2 + k2 - 1;
            if ((unsigned)p2 >= 24u) continue;
            #pragma unroll 1
            for (int k3 = 0; k3 < 3; ++k3) {
                int p3 = s3 + k3 - 1;
                if ((unsigned)p3 >= 24u) continue;
                int xoff = p1 * S1STR + p2 * S2STR + p3 * S3STR + w0;
                int tap0 = ((k1 * 3 + k2) * 3 + k3) * 3;
                const float* wbase = wsm + tap0 * (CIN * COUT);
                #pragma unroll
                for (int c = 0; c < CIN; ++c) {
                    const float* px = xb + c * STOT + xoff;
                    // interior 4 positions: one aligned LDG.128 (w0 % 4 == 0)
                    float4 mid = *reinterpret_cast<const float4*>(px);
                    float f0 = vlo ? px[-1] : 0.f;
                    float f5 = vhi ? px[4]  : 0.f;
                    u64 d[6];
                    d[0] = dup2(f0);
                    d[1] = dup2(mid.x); d[2] = dup2(mid.y);
                    d[3] = dup2(mid.z); d[4] = dup2(mid.w);
                    d[5] = dup2(f5);
                    #pragma unroll
                    for (int k4 = 0; k4 < 3; ++k4) {
                        const ulonglong2* wp2 = reinterpret_cast<const ulonglong2*>(
                            wbase + (k4 * CIN + c) * COUT);
                        ulonglong2 wv0 = wp2[0];
                        ulonglong2 wv1 = wp2[1];
                        ulonglong2 wv2 = wp2[2];
                        ulonglong2 wv3 = wp2[3];
                        #pragma unroll
                        for (int wi = 0; wi < 4; ++wi) {
                            u64 xv = d[wi + k4];
                            acc[wi][0] = fma2(xv, wv0.x, acc[wi][0]);
                            acc[wi][1] = fma2(xv, wv0.y, acc[wi][1]);
                            acc[wi][2] = fma2(xv, wv1.x, acc[wi][2]);
                            acc[wi][3] = fma2(xv, wv1.y, acc[wi][3]);
                            acc[wi][4] = fma2(xv, wv2.x, acc[wi][4]);
                            acc[wi][5] = fma2(xv, wv2.y, acc[wi][5]);
                            acc[wi][6] = fma2(xv, wv3.x, acc[wi][6]);
                            acc[wi][7] = fma2(xv, wv3.y, acc[wi][7]);
                        }
                    }
                }
            }
        }
    }

    // stores: 4 consecutive s4 outputs -> one STG.128 per output channel
    int sb = s1 * S1STR + s2 * S2STR + s3 * S3STR + w0;
    float4* ob = reinterpret_cast<float4*>(out + (size_t)b * OIMG + sb);
    #pragma unroll
    for (int op = 0; op < 8; ++op) {
        float lo0, hi0, lo1, hi1, lo2, hi2, lo3, hi3;
        unpack2(acc[0][op], lo0, hi0);
        unpack2(acc[1][op], lo1, hi1);
        unpack2(acc[2][op], lo2, hi2);
        unpack2(acc[3][op], lo3, hi3);
        ob[(size_t)(2 * op)     * (STOT / 4)] = make_float4(lo0, lo1, lo2, lo3);
        ob[(size_t)(2 * op + 1) * (STOT / 4)] = make_float4(hi0, hi1, hi2, hi3);
    }
}

extern "C" void kernel_launch(void* const* d_in, const int* in_sizes, int n_in,
                              void* d_out, int out_size) {
    const float* x    = (const float*)d_in[0];
    const float* wgt  = (const float*)d_in[1];
    const float* bias = (const float*)d_in[2];
    float* out = (float*)d_out;
    (void)in_sizes; (void)n_in; (void)out_size;

    dim3 block(128);
    dim3 grid(NWORK / 128);   // 5184
    conv4d_kernel<<<grid, block>>>(x, wgt, bias, out);
}

// round 7
// speedup vs baseline: 2.1966x; 1.6600x over previous
#include <cuda_runtime.h>
#include <cstdint>

#define S1STR   13824
#define S2STR   576
#define STOT    331776          // 24^4
#define CIN     8
#define COUT    16
#define XIMG    (CIN * STOT)
#define OIMG    (COUT * STOT)

#define THREADS 288             // 9 warps
#define NBLK    (8 * 24 * 24)   // 4608 blocks: one (b,s1,s2) plane each

// padded x plane in smem: per channel 26 rows x 32 cols = 832 -> pad to 840 words
#define XPW     840             // channel-plane stride (words), 840 % 32 == 8
#define XS_W    (CIN * XPW)     // 6720 words
#define WS_W    (81 * 128)      // wsm[tap*128 + c*16 + o], 10368 words
#define SMEM_BYTES ((XS_W + WS_W) * 4)   // 68352
#define EPI_STR 580             // epilogue [o][pos] stride

__device__ __forceinline__ unsigned tf32r(float f) {
    unsigned r; asm("cvt.rna.tf32.f32 %0, %1;" : "=r"(r) : "f"(f)); return r;
}

__device__ __forceinline__ void mma_tf32(float d[4],
                                         unsigned a0, unsigned a1,
                                         unsigned a2, unsigned a3,
                                         unsigned b0, unsigned b1) {
    asm volatile(
        "mma.sync.aligned.m16n8k8.row.col.f32.tf32.tf32.f32 "
        "{%0,%1,%2,%3}, {%4,%5,%6,%7}, {%8,%9}, {%0,%1,%2,%3};"
        : "+f"(d[0]), "+f"(d[1]), "+f"(d[2]), "+f"(d[3])
        : "r"(a0), "r"(a1), "r"(a2), "r"(a3), "r"(b0), "r"(b1));
}

__global__ __launch_bounds__(THREADS, 2)
void conv4d_mma_kernel(const float* __restrict__ x,
                       const float* __restrict__ w,
                       const float* __restrict__ bias,
                       float* __restrict__ out) {
    extern __shared__ float smem[];
    float* xs  = smem;           // XS_W words
    float* wsm = smem + XS_W;    // WS_W words

    const int tid  = threadIdx.x;
    const int lane = tid & 31;
    const int warp = tid >> 5;          // 0..8
    const int tg   = lane & 3;          // thread-in-group (k index base)
    const int grp  = lane >> 2;         // group id

    int bid = blockIdx.x;
    int s2 = bid % 24; int t = bid / 24;
    int s1 = t % 24;   int b = t / 24;

    // ---- stage weights as tf32, zero the x plane ----
    for (int i = tid; i < WS_W; i += THREADS) {
        int o = i & 15, c = (i >> 4) & 7, tap = i >> 7;
        wsm[i] = __uint_as_float(tf32r(w[o * 648 + tap * 8 + c]));
    }
    for (int i = tid; i < XS_W; i += THREADS) xs[i] = 0.0f;

    // ---- accumulators (bias-initialized) : d[mtile][nhalf][4] ----
    float bv0 = bias[2 * tg],     bv1 = bias[2 * tg + 1];
    float bv2 = bias[2 * tg + 8], bv3 = bias[2 * tg + 9];
    float d[4][2][4];
    #pragma unroll
    for (int i = 0; i < 4; ++i) {
        d[i][0][0] = bv0; d[i][0][1] = bv1; d[i][0][2] = bv0; d[i][0][3] = bv1;
        d[i][1][0] = bv2; d[i][1][1] = bv3; d[i][1][2] = bv2; d[i][1][3] = bv3;
    }

    // ---- per-mtile A base word addresses ----
    // staged x[s3][s4] lives at row s3+1, col s4+4. For tap offset k3*32+k4 to
    // read x[s3+k3-1][s4+k4-1], base must sit at row s3, col s4+3.
    int A0[4], A1[4];
    #pragma unroll
    for (int i = 0; i < 4; ++i) {
        int P0 = (warp * 4 + i) * 16 + grp;
        int P1 = P0 + 8;
        A0[i] = tg * XPW + (P0 / 24) * 32 + (P0 % 24) + 3;
        A1[i] = tg * XPW + (P1 / 24) * 32 + (P1 % 24) + 3;
    }
    __syncthreads();

    const float* __restrict__ xb = x + (size_t)b * XIMG;

    #pragma unroll 1
    for (int k1 = 0; k1 < 3; ++k1) {
        int p1 = s1 + k1 - 1;
        if ((unsigned)p1 >= 24u) continue;
        #pragma unroll 1
        for (int k2 = 0; k2 < 3; ++k2) {
            int p2 = s2 + k2 - 1;
            if ((unsigned)p2 >= 24u) continue;

            __syncthreads();   // previous compute done before overwriting xs
            // ---- stage one padded plane (tf32-rounded), coalesced ----
            const float* src = xb + p1 * S1STR + p2 * S2STR;
            #pragma unroll
            for (int i = 0; i < 4; ++i) {
                int j = i * THREADS + tid;      // 0..1151, lane-adjacent
                int row = j / 6, seg = j % 6;   // row = c*24 + s3
                int c = row / 24, s3 = row % 24;
                float4 v = *reinterpret_cast<const float4*>(
                    src + c * STOT + s3 * 24 + seg * 4);
                float4 cv;
                cv.x = __uint_as_float(tf32r(v.x));
                cv.y = __uint_as_float(tf32r(v.y));
                cv.z = __uint_as_float(tf32r(v.z));
                cv.w = __uint_as_float(tf32r(v.w));
                *reinterpret_cast<float4*>(
                    &xs[c * XPW + (s3 + 1) * 32 + 4 + seg * 4]) = cv;
            }
            __syncthreads();

            // ---- B fragments for the 9 taps of this (k1,k2) ----
            int tb = (k1 * 3 + k2) * 9;
            unsigned B0[9][2], B1[9][2];
            #pragma unroll
            for (int t9 = 0; t9 < 9; ++t9) {
                int base = (tb + t9) * 128 + tg * 16 + grp;
                B0[t9][0] = __float_as_uint(wsm[base]);          // k=tg,   n=grp
                B1[t9][0] = __float_as_uint(wsm[base + 64]);     // k=tg+4, n=grp
                B0[t9][1] = __float_as_uint(wsm[base + 8]);      // k=tg,   n=grp+8
                B1[t9][1] = __float_as_uint(wsm[base + 72]);     // k=tg+4, n=grp+8
            }

            // ---- compute: 4 m-tiles x 9 taps x 2 n-halves ----
            #pragma unroll
            for (int i = 0; i < 4; ++i) {
                #pragma unroll
                for (int t9 = 0; t9 < 9; ++t9) {
                    int off = (t9 / 3) * 32 + (t9 % 3);   // k3*32 + k4
                    unsigned a0 = __float_as_uint(xs[A0[i] + off]);
                    unsigned a1 = __float_as_uint(xs[A1[i] + off]);
                    unsigned a2 = __float_as_uint(xs[A0[i] + off + 4 * XPW]);
                    unsigned a3 = __float_as_uint(xs[A1[i] + off + 4 * XPW]);
                    mma_tf32(d[i][0], a0, a1, a2, a3, B0[t9][0], B1[t9][0]);
                    mma_tf32(d[i][1], a0, a1, a2, a3, B0[t9][1], B1[t9][1]);
                }
            }
        }
    }

    // ---- epilogue: transpose via smem, coalesced STG.128 ----
    size_t ob = (size_t)b * OIMG + (size_t)(s1 * S1STR + s2 * S2STR);
    #pragma unroll 1
    for (int half = 0; half < 2; ++half) {
        __syncthreads();
        #pragma unroll
        for (int i = 0; i < 4; ++i) {
            int P0 = (warp * 4 + i) * 16 + grp;
            int P1 = P0 + 8;
            int o0 = 2 * tg;
            xs[o0 * EPI_STR + P0]       = d[i][half][0];
            xs[(o0 + 1) * EPI_STR + P0] = d[i][half][1];
            xs[o0 * EPI_STR + P1]       = d[i][half][2];
            xs[(o0 + 1) * EPI_STR + P1] = d[i][half][3];
        }
        __syncthreads();
        int o  = tid / 36;       // 0..7
        int ch = tid % 36;       // 16-float chunk within the 576-pos plane
        const float4* se = reinterpret_cast<const float4*>(&xs[o * EPI_STR + ch * 16]);
        float4* de = reinterpret_cast<float4*>(
            out + ob + (size_t)(half * 8 + o) * STOT + ch * 16);
        de[0] = se[0]; de[1] = se[1]; de[2] = se[2]; de[3] = se[3];
    }
}

extern "C" void kernel_launch(void* const* d_in, const int* in_sizes, int n_in,
                              void* d_out, int out_size) {
    const float* x    = (const float*)d_in[0];
    const float* wgt  = (const float*)d_in[1];
    const float* bias = (const float*)d_in[2];
    float* out = (float*)d_out;
    (void)in_sizes; (void)n_in; (void)out_size;

    cudaFuncSetAttribute(conv4d_mma_kernel,
                         cudaFuncAttributeMaxDynamicSharedMemorySize, SMEM_BYTES);
    conv4d_mma_kernel<<<NBLK, THREADS, SMEM_BYTES>>>(x, wgt, bias, out);
}